// round 16
// baseline (speedup 1.0000x reference)
#include <cuda_runtime.h>
#include <math.h>
#include <stdint.h>

#define HID 128
#define NMAX 50000
#define EMAX 500000
#define NRBF 20
#define PI_OVER_CUT 0.5235987755982988f   // pi / 6
#define CUTOFF 6.0f

typedef unsigned long long u64;

// ---------------- scratch (device globals; no runtime allocation) ----------------
__device__ float g_ns[NMAX * HID];
__device__ float g_nv[NMAX * 3 * HID];
__device__ float g_nvold[NMAX * 3 * HID];
__device__ float g_tmpH[NMAX * HID];
__device__ float g_smsg[NMAX * 3 * HID];
__device__ float g_Uv[NMAX * 3 * HID];
__device__ float g_Vv[NMAX * 3 * HID];
__device__ float g_Vn[NMAX * HID];
__device__ float g_inner[NMAX * HID];
__device__ float g_abuf[NMAX * 3 * HID];

__device__ int   g_act_r[EMAX];
__device__ int   g_act_c[EMAX];
__device__ float g_act_unit[EMAX * 3];
__device__ float g_act_rbf[EMAX * NRBF];
__device__ float g_act_fcut[EMAX];
__device__ int   g_nact;

__device__ __forceinline__ float silu_f(float x) {
    return x / (1.0f + __expf(-x));
}

// packed f32x2 helpers (sm_100+; SASS FFMA2)
__device__ __forceinline__ u64 fma2(u64 a, u64 b, u64 c) {
    u64 d;
    asm("fma.rn.f32x2 %0, %1, %2, %3;" : "=l"(d) : "l"(a), "l"(b), "l"(c));
    return d;
}
__device__ __forceinline__ u64 dup2(float x) {
    u64 d;
    asm("mov.b64 %0, {%1, %1};" : "=l"(d) : "f"(x));
    return d;
}
__device__ __forceinline__ void unpack2(u64 v, float& lo, float& hi) {
    asm("mov.b64 {%0, %1}, %2;" : "=f"(lo), "=f"(hi) : "l"(v));
}

// warp footprint: ty = (w&3)*4 + (l&3) in 0..15 (8 rows each), tx = (w>>2)*8 + (l>>2)
// in 0..15 (4 cols each). Per warp per k-step unique smem: a=128B, b=128B.
__device__ __forceinline__ void tile_coords(int tid, int& tx, int& ty) {
    int w = tid >> 5, l = tid & 31;
    ty = (w & 3) * 4 + (l & 3);    // 0..15 -> row group of 8
    tx = (w >> 2) * 8 + (l >> 2);  // 0..15 -> col group of 4
}

// ---------------- reset ----------------
__global__ void reset_kernel() { g_nact = 0; }

// ---------------- edge geometry + compaction ----------------
__global__ void edge_geom_kernel(const float* __restrict__ pos,
                                 const float* __restrict__ cell,
                                 const int* __restrict__ ei,
                                 const int* __restrict__ offs,
                                 float* __restrict__ out_dist,
                                 float* __restrict__ out_ei,
                                 int E) {
    int e = blockIdx.x * blockDim.x + threadIdx.x;
    if (e >= E) return;
    int r = ei[e];
    int c = ei[E + e];
    float o0 = (float)offs[e * 3 + 0];
    float o1 = (float)offs[e * 3 + 1];
    float o2 = (float)offs[e * 3 + 2];
    float ox = o0 * cell[0] + o1 * cell[3] + o2 * cell[6];
    float oy = o0 * cell[1] + o1 * cell[4] + o2 * cell[7];
    float oz = o0 * cell[2] + o1 * cell[5] + o2 * cell[8];
    float dx = pos[r * 3 + 0] - pos[c * 3 + 0] + ox;
    float dy = pos[r * 3 + 1] - pos[c * 3 + 1] + oy;
    float dz = pos[r * 3 + 2] - pos[c * 3 + 2] + oz;
    float dist = sqrtf(dx * dx + dy * dy + dz * dz);
    out_dist[e] = dist;
    out_ei[e] = (float)r;
    out_ei[E + e] = (float)c;

    if (dist < CUTOFF) {
        int idx = atomicAdd(&g_nact, 1);
        g_act_r[idx] = r;
        g_act_c[idx] = c;
        float inv = 1.0f / dist;
        g_act_unit[idx * 3 + 0] = dx * inv;
        g_act_unit[idx * 3 + 1] = dy * inv;
        g_act_unit[idx * 3 + 2] = dz * inv;
        g_act_fcut[idx] = 0.5f * (cosf(dist * PI_OVER_CUT) + 1.0f);
#pragma unroll
        for (int t = 0; t < NRBF; t++) {
            g_act_rbf[idx * NRBF + t] = sinf(dist * (float)(t + 1) * PI_OVER_CUT) * inv;
        }
    }
}

// ---------------- node init: ns = embed[z], nv = nvold = 0 ----------------
__global__ void init_nodes_kernel(const float* __restrict__ embed,
                                  const int* __restrict__ z,
                                  int N) {
    int t = blockIdx.x * blockDim.x + threadIdx.x;
    if (t >= N * HID) return;
    int n = t >> 7;
    int h = t & 127;
    g_ns[t] = embed[z[n] * HID + h];
    int base = n * 3 * HID + h;
    g_nv[base] = 0.0f;
    g_nv[base + HID] = 0.0f;
    g_nv[base + 2 * HID] = 0.0f;
    g_nvold[base] = 0.0f;
    g_nvold[base + HID] = 0.0f;
    g_nvold[base + 2 * HID] = 0.0f;
}

// ================= GEMM core (BM=128, BN=64, BK=16, 256 thr, 8x4 micro) =================
// 2-stage smem ping-pong (1 barrier/k-step), FFMA2 inner product, 3 CTAs/SM.

__device__ __forceinline__ void gemm_compute_step(const float (*As)[132],
                                                  const float (*Bs)[68],
                                                  int tx, int ty,
                                                  u64 acc2[8][2]) {
#pragma unroll
    for (int k = 0; k < 16; k++) {
        float a[8];
        *(float4*)&a[0] = *(const float4*)&As[k][ty * 8];
        *(float4*)&a[4] = *(const float4*)&As[k][ty * 8 + 4];
        float4 bv = *(const float4*)&Bs[k][tx * 4];
        u64 bp0 = *(const u64*)&bv.x;
        u64 bp1 = *(const u64*)&bv.z;
#pragma unroll
        for (int i = 0; i < 8; i++) {
            u64 ad = dup2(a[i]);
            acc2[i][0] = fma2(ad, bp0, acc2[i][0]);
            acc2[i][1] = fma2(ad, bp1, acc2[i][1]);
        }
    }
}

__device__ __forceinline__ void gemm_store_tile(float (*As)[132], float (*Bs)[68],
                                                const float4 apre[2], float4 bpre,
                                                int arow, int acol, int brow, int bcol) {
#pragma unroll
    for (int g = 0; g < 2; g++) {
        int m = arow + g * 64;
        As[acol + 0][m] = apre[g].x;
        As[acol + 1][m] = apre[g].y;
        As[acol + 2][m] = apre[g].z;
        As[acol + 3][m] = apre[g].w;
    }
    *(float4*)&Bs[brow][bcol] = bpre;
}

template <bool ACCUM, bool BIAS, bool SILU>
__device__ __forceinline__ void gemm_epilogue(u64 acc2[8][2],
                                              const float* __restrict__ bias,
                                              float* __restrict__ C,
                                              int r0, int c0, int tx, int ty,
                                              int N, int M) {
#pragma unroll
    for (int i = 0; i < 8; i++) {
        int row = r0 + ty * 8 + i;
        if (row < N) {
            int col = c0 + tx * 4;
            if (col < M) {
                float v0, v1, v2, v3;
                unpack2(acc2[i][0], v0, v1);
                unpack2(acc2[i][1], v2, v3);
                float* cp = C + (size_t)row * M + col;
                if (ACCUM) {
                    float4 pv = *(const float4*)cp;
                    v0 += pv.x; v1 += pv.y; v2 += pv.z; v3 += pv.w;
                }
                if (BIAS) {
                    float4 bv = *(const float4*)(bias + col);
                    v0 += bv.x; v1 += bv.y; v2 += bv.z; v3 += bv.w;
                }
                if (SILU) {
                    v0 = silu_f(v0); v1 = silu_f(v1);
                    v2 = silu_f(v2); v3 = silu_f(v3);
                }
                *(float4*)cp = make_float4(v0, v1, v2, v3);
            }
        }
    }
}

// ---------------- generic fp32 GEMM: C = [act](([C] +) A@B (+ bias)) ----------------
// A: [N,K] row-major, B: [K,M] row-major, C: [N,M].
template <bool ACCUM, bool BIAS, bool SILU>
__global__ void __launch_bounds__(256, 3) gemm128_kernel(const float* __restrict__ A,
                                                         const float* __restrict__ B,
                                                         const float* __restrict__ bias,
                                                         float* __restrict__ C,
                                                         int N, int K, int M) {
    __shared__ float As[2][16][132];
    __shared__ float Bs[2][16][68];
    int tid = threadIdx.x;
    int r0 = blockIdx.y * 128;
    int c0 = blockIdx.x * 64;
    int tx, ty;
    tile_coords(tid, tx, ty);

    u64 acc2[8][2];
#pragma unroll
    for (int i = 0; i < 8; i++) { acc2[i][0] = 0ULL; acc2[i][1] = 0ULL; }

    int arow = tid >> 2;          // 0..63
    int acol = (tid & 3) * 4;     // 0,4,8,12
    int brow = tid >> 4;          // 0..15
    int bcol = (tid & 15) * 4;    // 0..60

    float4 apre[2], bpre;
#pragma unroll
    for (int g = 0; g < 2; g++) {
        int grow = r0 + arow + g * 64;
        apre[g] = make_float4(0.f, 0.f, 0.f, 0.f);
        if (grow < N) apre[g] = *(const float4*)(A + (size_t)grow * K + acol);
    }
    {
        int gcol = c0 + bcol;
        bpre = make_float4(0.f, 0.f, 0.f, 0.f);
        if (gcol < M) bpre = *(const float4*)(B + (size_t)brow * M + gcol);
    }
    gemm_store_tile(As[0], Bs[0], apre, bpre, arow, acol, brow, bcol);
    __syncthreads();

    int nsteps = K >> 4;
    for (int step = 0; step < nsteps; step++) {
        int cur = step & 1;
        bool more = (step + 1 < nsteps);
        if (more) {
            int kk = (step + 1) << 4;
#pragma unroll
            for (int g = 0; g < 2; g++) {
                int grow = r0 + arow + g * 64;
                apre[g] = make_float4(0.f, 0.f, 0.f, 0.f);
                if (grow < N) apre[g] = *(const float4*)(A + (size_t)grow * K + kk + acol);
            }
            int gcol = c0 + bcol;
            bpre = make_float4(0.f, 0.f, 0.f, 0.f);
            if (gcol < M) bpre = *(const float4*)(B + (size_t)(kk + brow) * M + gcol);
        }
        gemm_compute_step(As[cur], Bs[cur], tx, ty, acc2);
        if (more) {
            gemm_store_tile(As[cur ^ 1], Bs[cur ^ 1], apre, bpre, arow, acol, brow, bcol);
            __syncthreads();
        }
    }

    gemm_epilogue<ACCUM, BIAS, SILU>(acc2, bias, C, r0, c0, tx, ty, N, M);
}

// ---------------- fused U/V projection: blockIdx.z selects (B,C) pair ----------------
// A: [N,128] shared; z=0: C0 = A@B0 ; z=1: C1 = A@B1. K=M=128 fixed, BN=64 => grid.x=2.
__global__ void __launch_bounds__(256, 3) gemm_uv_kernel(const float* __restrict__ A,
                                                         const float* __restrict__ B0,
                                                         const float* __restrict__ B1,
                                                         float* __restrict__ C0,
                                                         float* __restrict__ C1,
                                                         int N) {
    const float* B = (blockIdx.z == 0) ? B0 : B1;
    float* C = (blockIdx.z == 0) ? C0 : C1;

    __shared__ float As[2][16][132];
    __shared__ float Bs[2][16][68];
    int tid = threadIdx.x;
    int r0 = blockIdx.y * 128;
    int c0 = blockIdx.x * 64;
    int tx, ty;
    tile_coords(tid, tx, ty);

    u64 acc2[8][2];
#pragma unroll
    for (int i = 0; i < 8; i++) { acc2[i][0] = 0ULL; acc2[i][1] = 0ULL; }

    int arow = tid >> 2;
    int acol = (tid & 3) * 4;
    int brow = tid >> 4;
    int bcol = (tid & 15) * 4;

    float4 apre[2], bpre;
#pragma unroll
    for (int g = 0; g < 2; g++) {
        int grow = r0 + arow + g * 64;
        apre[g] = make_float4(0.f, 0.f, 0.f, 0.f);
        if (grow < N) apre[g] = *(const float4*)(A + (size_t)grow * 128 + acol);
    }
    bpre = *(const float4*)(B + (size_t)brow * 128 + c0 + bcol);
    gemm_store_tile(As[0], Bs[0], apre, bpre, arow, acol, brow, bcol);
    __syncthreads();

    for (int step = 0; step < 8; step++) {
        int cur = step & 1;
        bool more = (step + 1 < 8);
        if (more) {
            int kk = (step + 1) << 4;
#pragma unroll
            for (int g = 0; g < 2; g++) {
                int grow = r0 + arow + g * 64;
                apre[g] = make_float4(0.f, 0.f, 0.f, 0.f);
                if (grow < N) apre[g] = *(const float4*)(A + (size_t)grow * 128 + kk + acol);
            }
            bpre = *(const float4*)(B + (size_t)(kk + brow) * 128 + c0 + bcol);
        }
        gemm_compute_step(As[cur], Bs[cur], tx, ty, acc2);
        if (more) {
            gemm_store_tile(As[cur ^ 1], Bs[cur ^ 1], apre, bpre, arow, acol, brow, bcol);
            __syncthreads();
        }
    }

    gemm_epilogue<false, false, false>(acc2, nullptr, C, r0, c0, tx, ty, N, 128);
}

// ---------------- dual-A GEMM: C = silu([A1|A2] @ B + bias) ----------------
// A1,A2: [N,128]; B: [256,128]; C: [N,128]. K=256 (steps 0..7 A1, 8..15 A2). BN=64.
__global__ void __launch_bounds__(256, 3) gemm_dualA_kernel(const float* __restrict__ A1,
                                                            const float* __restrict__ A2,
                                                            const float* __restrict__ B,
                                                            const float* __restrict__ bias,
                                                            float* __restrict__ C,
                                                            int N) {
    __shared__ float As[2][16][132];
    __shared__ float Bs[2][16][68];
    int tid = threadIdx.x;
    int r0 = blockIdx.y * 128;
    int c0 = blockIdx.x * 64;
    int tx, ty;
    tile_coords(tid, tx, ty);

    u64 acc2[8][2];
#pragma unroll
    for (int i = 0; i < 8; i++) { acc2[i][0] = 0ULL; acc2[i][1] = 0ULL; }

    int arow = tid >> 2;
    int acol = (tid & 3) * 4;
    int brow = tid >> 4;
    int bcol = (tid & 15) * 4;

    float4 apre[2], bpre;
#pragma unroll
    for (int g = 0; g < 2; g++) {
        int grow = r0 + arow + g * 64;
        apre[g] = make_float4(0.f, 0.f, 0.f, 0.f);
        if (grow < N) apre[g] = *(const float4*)(A1 + (size_t)grow * 128 + acol);
    }
    bpre = *(const float4*)(B + (size_t)brow * 128 + c0 + bcol);
    gemm_store_tile(As[0], Bs[0], apre, bpre, arow, acol, brow, bcol);
    __syncthreads();

    for (int step = 0; step < 16; step++) {
        int cur = step & 1;
        bool more = (step + 1 < 16);
        if (more) {
            int kk = (step + 1) << 4;
            const float* Ap = (kk < 128) ? A1 : A2;
            int ak = kk & 127;
#pragma unroll
            for (int g = 0; g < 2; g++) {
                int grow = r0 + arow + g * 64;
                apre[g] = make_float4(0.f, 0.f, 0.f, 0.f);
                if (grow < N) apre[g] = *(const float4*)(Ap + (size_t)grow * 128 + ak + acol);
            }
            bpre = *(const float4*)(B + (size_t)(kk + brow) * 128 + c0 + bcol);
        }
        gemm_compute_step(As[cur], Bs[cur], tx, ty, acc2);
        if (more) {
            gemm_store_tile(As[cur ^ 1], Bs[cur ^ 1], apre, bpre, arow, acol, brow, bcol);
            __syncthreads();
        }
    }

    gemm_epilogue<false, true, true>(acc2, bias, C, r0, c0, tx, ty, N, 128);
}

// ---------------- edge messages (active edges only, warp per edge) ----------------
__global__ void edge_msg_kernel(const float* __restrict__ W,   // [20,384] for layer l
                                const float* __restrict__ b,   // [384]
                                const float* __restrict__ s) { // [N,384]
    int lane = threadIdx.x & 31;
    int warp = (blockIdx.x * blockDim.x + threadIdx.x) >> 5;
    int nwarps = (gridDim.x * blockDim.x) >> 5;
    int nact = g_nact;
    for (int e = warp; e < nact; e += nwarps) {
        int r = g_act_r[e];
        int c = g_act_c[e];
        float fcut = g_act_fcut[e];
        float u0 = g_act_unit[e * 3 + 0];
        float u1 = g_act_unit[e * 3 + 1];
        float u2 = g_act_unit[e * 3 + 2];
        float rbf[NRBF];
#pragma unroll
        for (int t = 0; t < NRBF; t++) rbf[t] = g_act_rbf[e * NRBF + t];

        float fout[12];
#pragma unroll
        for (int p = 0; p < 12; p++) {
            int j = lane + p * 32;
            float f = b[j];
#pragma unroll
            for (int t = 0; t < NRBF; t++) f += rbf[t] * W[t * 384 + j];
            fout[p] = f * fcut * s[(size_t)c * 384 + j];
        }
#pragma unroll
        for (int q = 0; q < 4; q++) {
            int h = lane + q * 32;
            float gsv = fout[q];
            float gev = fout[4 + q];
            float msg = fout[8 + q];
            atomicAdd(&g_ns[r * HID + h], msg);
            int rb = r * 3 * HID + h;
            int cb = c * 3 * HID + h;
            atomicAdd(&g_nv[rb], g_nvold[cb] * gsv + gev * u0);
            atomicAdd(&g_nv[rb + HID], g_nvold[cb + HID] * gsv + gev * u1);
            atomicAdd(&g_nv[rb + 2 * HID], g_nvold[cb + 2 * HID] * gsv + gev * u2);
        }
    }
}

// ---------------- Vnorm + inner product ----------------
__global__ void vnorm_inner_kernel(int N) {
    int t = blockIdx.x * blockDim.x + threadIdx.x;
    if (t >= N * HID) return;
    int n = t >> 7;
    int h = t & 127;
    size_t base = (size_t)n * 3 * HID + h;
    float u0 = g_Uv[base], u1 = g_Uv[base + HID], u2 = g_Uv[base + 2 * HID];
    float v0 = g_Vv[base], v1 = g_Vv[base + HID], v2 = g_Vv[base + 2 * HID];
    g_Vn[t] = sqrtf(v0 * v0 + v1 * v1 + v2 * v2);
    g_inner[t] = u0 * v0 + u1 * v1 + u2 * v2;
}

// -------- final update: nv += a_vv*Uv ; ns += inner*a_sv + a_ss ; nvold = nv --------
__global__ void update_kernel(int N) {
    int t = blockIdx.x * blockDim.x + threadIdx.x;
    if (t >= N * HID) return;
    int n = t >> 7;
    int h = t & 127;
    size_t base = (size_t)n * 3 * HID + h;
    float avv = g_abuf[base];
    float asv = g_abuf[base + HID];
    float ass = g_abuf[base + 2 * HID];
    float n0 = g_nv[base]           + avv * g_Uv[base];
    float n1 = g_nv[base + HID]     + avv * g_Uv[base + HID];
    float n2 = g_nv[base + 2 * HID] + avv * g_Uv[base + 2 * HID];
    g_nv[base] = n0;            g_nvold[base] = n0;
    g_nv[base + HID] = n1;      g_nvold[base + HID] = n1;
    g_nv[base + 2 * HID] = n2;  g_nvold[base + 2 * HID] = n2;
    g_ns[t] += g_inner[t] * asv + ass;
}

// ---------------- head second layer (matvec over 64) ----------------
__global__ void head2_kernel(const float* __restrict__ w,  // [64]
                             const float* __restrict__ b,  // [1]
                             float* __restrict__ out_v, int N) {
    int n = blockIdx.x * blockDim.x + threadIdx.x;
    if (n >= N) return;
    float acc = b[0];
    const float* h = g_tmpH + (size_t)n * 64;
#pragma unroll
    for (int i = 0; i < 64; i++) acc += h[i] * w[i];
    out_v[n] = acc;
}

// ---------------- launch ----------------
static inline dim3 gemm_grid(int M, int N) {
    return dim3((M + 63) / 64, (N + 127) / 128);
}

extern "C" void kernel_launch(void* const* d_in, const int* in_sizes, int n_in,
                              void* d_out, int out_size) {
    const int*   z        = (const int*)d_in[0];
    const float* pos      = (const float*)d_in[1];
    const float* cell     = (const float*)d_in[2];
    const int*   ei       = (const int*)d_in[3];
    const int*   offs     = (const int*)d_in[4];
    const float* embed    = (const float*)d_in[5];
    const float* mfW      = (const float*)d_in[6];   // [3,20,384]
    const float* mfb      = (const float*)d_in[7];   // [3,384]
    const float* mW1      = (const float*)d_in[8];   // [3,128,128]
    const float* mb1      = (const float*)d_in[9];
    const float* mW2      = (const float*)d_in[10];  // [3,128,384]
    const float* mb2      = (const float*)d_in[11];
    const float* uU       = (const float*)d_in[12];  // [3,128,128]
    const float* uV       = (const float*)d_in[13];
    const float* uW1      = (const float*)d_in[14];  // [3,256,128]
    const float* ub1      = (const float*)d_in[15];
    const float* uW2      = (const float*)d_in[16];  // [3,128,384]
    const float* ub2      = (const float*)d_in[17];
    const float* hW1      = (const float*)d_in[18];  // [128,64]
    const float* hb1      = (const float*)d_in[19];
    const float* hW2      = (const float*)d_in[20];  // [64]
    const float* hb2      = (const float*)d_in[21];

    int N = in_sizes[0];
    int E = in_sizes[3] / 2;

    float* out   = (float*)d_out;
    float* out_v = out;                  // [N]
    float* out_p = out + N;              // [N*3]
    float* out_e = out + 4 * N;          // [2*E]
    float* out_d = out + 4 * N + 2 * E;  // [E]

    void* p;
    cudaGetSymbolAddress(&p, g_ns);    float* ns    = (float*)p;
    cudaGetSymbolAddress(&p, g_nv);    float* nv    = (float*)p;
    cudaGetSymbolAddress(&p, g_tmpH);  float* tmpH  = (float*)p;
    cudaGetSymbolAddress(&p, g_smsg);  float* smsg  = (float*)p;
    cudaGetSymbolAddress(&p, g_Uv);    float* Uv    = (float*)p;
    cudaGetSymbolAddress(&p, g_Vv);    float* Vv    = (float*)p;
    cudaGetSymbolAddress(&p, g_Vn);    float* Vn    = (float*)p;
    cudaGetSymbolAddress(&p, g_abuf);  float* abuf  = (float*)p;

    reset_kernel<<<1, 1>>>();
    edge_geom_kernel<<<(E + 255) / 256, 256>>>(pos, cell, ei, offs, out_d, out_e, E);
    init_nodes_kernel<<<(N * HID + 255) / 256, 256>>>(embed, z, N);
    cudaMemcpyAsync(out_p, pos, (size_t)N * 3 * sizeof(float), cudaMemcpyDeviceToDevice);

    for (int l = 0; l < 3; l++) {
        const float* lmfW = mfW + (size_t)l * 20 * 384;
        const float* lmfb = mfb + (size_t)l * 384;

        // s = silu(ns @ mW1 + mb1) @ mW2 + mb2
        gemm128_kernel<false, true, true><<<gemm_grid(128, N), 256>>>(
            ns, mW1 + (size_t)l * 128 * 128, mb1 + (size_t)l * 128, tmpH, N, 128, 128);
        gemm128_kernel<false, true, false><<<gemm_grid(384, N), 256>>>(
            tmpH, mW2 + (size_t)l * 128 * 384, mb2 + (size_t)l * 384, smsg, N, 128, 384);

        // edge messages read g_nvold (pre-message state, maintained by dual-write)
        edge_msg_kernel<<<256, 256>>>(lmfW, lmfb, smsg);

        // Uv = nv @ U ; Vv = nv @ V  (nv viewed as [3N,128]; fused, z selects B/C)
        {
            dim3 g(2, (3 * N + 127) / 128, 2);
            gemm_uv_kernel<<<g, 256>>>(nv,
                                       uU + (size_t)l * 128 * 128,
                                       uV + (size_t)l * 128 * 128,
                                       Uv, Vv, 3 * N);
        }

        vnorm_inner_kernel<<<(N * HID + 255) / 256, 256>>>(N);

        // hidden = silu([ns|Vn] @ uW1 + b1)   (dual-A, K=256, single pass)
        {
            dim3 g(2, (N + 127) / 128, 1);
            gemm_dualA_kernel<<<g, 256>>>(ns, Vn,
                                          uW1 + (size_t)l * 256 * 128,
                                          ub1 + (size_t)l * 128, tmpH, N);
        }
        // a = hidden @ W2 + b2
        gemm128_kernel<false, true, false><<<gemm_grid(384, N), 256>>>(
            tmpH, uW2 + (size_t)l * 128 * 384, ub2 + (size_t)l * 384, abuf, N, 128, 384);

        update_kernel<<<(N * HID + 255) / 256, 256>>>(N);
    }

    // head
    gemm128_kernel<false, true, true><<<gemm_grid(64, N), 256>>>(
        ns, hW1, hb1, tmpH, N, 128, 64);
    head2_kernel<<<(N + 255) / 256, 256>>>(hW2, hb2, out_v, N);
}

// round 17
// speedup vs baseline: 1.5923x; 1.5923x over previous
#include <cuda_runtime.h>
#include <cuda_bf16.h>
#include <math.h>
#include <stdint.h>

#define HID 128
#define NMAX 50000
#define EMAX 500000
#define NRBF 20
#define PI_OVER_CUT 0.5235987755982988f   // pi / 6
#define CUTOFF 6.0f

// ---------------- scratch (device globals; no runtime allocation) ----------------
__device__ float g_ns[NMAX * HID];
__device__ float g_nv[NMAX * 3 * HID];
__device__ float g_nvold[NMAX * 3 * HID];
__device__ float g_tmpH[NMAX * HID];
__device__ float g_smsg[NMAX * 3 * HID];
__device__ float g_Uv[NMAX * 3 * HID];
__device__ float g_Vv[NMAX * 3 * HID];
__device__ float g_Vn[NMAX * HID];
__device__ float g_inner[NMAX * HID];
__device__ float g_abuf[NMAX * 3 * HID];

__device__ int   g_act_r[EMAX];
__device__ int   g_act_c[EMAX];
__device__ float g_act_unit[EMAX * 3];
__device__ float g_act_rbf[EMAX * NRBF];
__device__ float g_act_fcut[EMAX];
__device__ int   g_nact;

__device__ __forceinline__ float silu_f(float x) {
    return x / (1.0f + __expf(-x));
}

// ---------------- mma.sync helpers (sm_80 baseline PTX; valid on compute_103) ------
__device__ __forceinline__ unsigned sptr(const void* p) {
    return (unsigned)__cvta_generic_to_shared(p);
}
__device__ __forceinline__ void ldm4(unsigned& d0, unsigned& d1, unsigned& d2,
                                     unsigned& d3, unsigned a) {
    asm volatile("ldmatrix.sync.aligned.m8n8.x4.shared.b16 {%0,%1,%2,%3}, [%4];"
                 : "=r"(d0), "=r"(d1), "=r"(d2), "=r"(d3) : "r"(a));
}
__device__ __forceinline__ void ldm4t(unsigned& d0, unsigned& d1, unsigned& d2,
                                      unsigned& d3, unsigned a) {
    asm volatile("ldmatrix.sync.aligned.m8n8.x4.trans.shared.b16 {%0,%1,%2,%3}, [%4];"
                 : "=r"(d0), "=r"(d1), "=r"(d2), "=r"(d3) : "r"(a));
}
__device__ __forceinline__ void mma16816(float* c, const unsigned* a, const unsigned* b) {
    asm volatile("mma.sync.aligned.m16n8k16.row.col.f32.bf16.bf16.f32 "
                 "{%0,%1,%2,%3}, {%4,%5,%6,%7}, {%8,%9}, {%0,%1,%2,%3};"
                 : "+f"(c[0]), "+f"(c[1]), "+f"(c[2]), "+f"(c[3])
                 : "r"(a[0]), "r"(a[1]), "r"(a[2]), "r"(a[3]), "r"(b[0]), "r"(b[1]));
}

// split fp32 -> bf16 hi + bf16 residual; 8 values -> two uint4 (2 bf16 per u32)
__device__ __forceinline__ void cvt8bf(float4 x0, float4 x1, uint4& h, uint4& l) {
    float xs[8] = {x0.x, x0.y, x0.z, x0.w, x1.x, x1.y, x1.z, x1.w};
    unsigned hh[8], ll[8];
#pragma unroll
    for (int i = 0; i < 8; i++) {
        __nv_bfloat16 hb = __float2bfloat16(xs[i]);
        float rem = xs[i] - __bfloat162float(hb);
        __nv_bfloat16 lb = __float2bfloat16(rem);
        hh[i] = (unsigned)__bfloat16_as_ushort(hb);
        ll[i] = (unsigned)__bfloat16_as_ushort(lb);
    }
    h = make_uint4(hh[0] | (hh[1] << 16), hh[2] | (hh[3] << 16),
                   hh[4] | (hh[5] << 16), hh[6] | (hh[7] << 16));
    l = make_uint4(ll[0] | (ll[1] << 16), ll[2] | (ll[3] << 16),
                   ll[4] | (ll[5] << 16), ll[6] | (ll[7] << 16));
}

// ================= MMA GEMM body: C = [act](A @ B + bias) =================
// A (row-stride 128): [N,128] (or [N,256] as A1|A2 when DUAL). B: [K,M] row-major.
// Block tile 128x128, BK=16, 256 thr = 8 warps (4m x 2n), warp tile 32x64.
// hi/lo bf16 split, fp32 accum: D = AhBh + AlBh + AhBl (albl term ~2^-18, dropped).
template <bool BIAS, bool SILU, bool DUAL>
__device__ __forceinline__ void mma_gemm_body(const float* __restrict__ A1,
                                              const float* __restrict__ A2,
                                              const float* __restrict__ B,
                                              const float* __restrict__ bias,
                                              float* __restrict__ C,
                                              int N, int M) {
    __shared__ __align__(16) unsigned short AsH[2][128][24];  // rows padded to 48B
    __shared__ __align__(16) unsigned short AsL[2][128][24];
    __shared__ __align__(16) unsigned short BsH[2][16][136];  // rows padded to 272B
    __shared__ __align__(16) unsigned short BsL[2][16][136];

    int tid = threadIdx.x;
    int lane = tid & 31, wid = tid >> 5;
    int wM = wid & 3, wN = wid >> 2;
    int r0 = blockIdx.y * 128, c0 = blockIdx.x * 128;

    int am = tid >> 1, aks = (tid & 1) << 3;    // A convert: row am, k-offset aks
    int bk = tid >> 4, bns = (tid & 15) << 3;   // B convert: k-row bk, n-offset bns
    int lj = lane >> 3, lr = lane & 7;          // ldmatrix lane mapping

    float acc[2][8][4];
#pragma unroll
    for (int mi = 0; mi < 2; mi++)
#pragma unroll
        for (int ni = 0; ni < 8; ni++)
#pragma unroll
            for (int q = 0; q < 4; q++) acc[mi][ni][q] = 0.0f;

    int nt = DUAL ? 16 : 8;
    float4 ax0, ax1, bx0, bx1;

    // ---- tile loaders ----
    auto loadA = [&](int t) {
        const float* Ap = (!DUAL || t < 8) ? A1 : A2;
        int kc = (t & 7) * 16;
        int row = r0 + am;
        ax0 = make_float4(0.f, 0.f, 0.f, 0.f); ax1 = ax0;
        if (row < N) {
            const float* p = Ap + (size_t)row * 128 + kc + aks;
            ax0 = *(const float4*)p;
            ax1 = *(const float4*)(p + 4);
        }
    };
    auto loadB = [&](int t) {
        int col = c0 + bns;
        bx0 = make_float4(0.f, 0.f, 0.f, 0.f); bx1 = bx0;
        if (col < M) {
            const float* p = B + (size_t)(t * 16 + bk) * M + col;
            bx0 = *(const float4*)p;
            bx1 = *(const float4*)(p + 4);
        }
    };
    auto storeTile = [&](int buf) {
        uint4 h, l;
        cvt8bf(ax0, ax1, h, l);
        *(uint4*)&AsH[buf][am][aks] = h;
        *(uint4*)&AsL[buf][am][aks] = l;
        cvt8bf(bx0, bx1, h, l);
        *(uint4*)&BsH[buf][bk][bns] = h;
        *(uint4*)&BsL[buf][bk][bns] = l;
    };

    auto compute = [&](int buf) {
        unsigned aH[2][4], aL[2][4], bb[8][2];
#pragma unroll
        for (int mi = 0; mi < 2; mi++) {
            int arow = wM * 32 + mi * 16 + (lj & 1) * 8 + lr;
            int acol = (lj >> 1) * 8;
            ldm4(aH[mi][0], aH[mi][1], aH[mi][2], aH[mi][3], sptr(&AsH[buf][arow][acol]));
            ldm4(aL[mi][0], aL[mi][1], aL[mi][2], aL[mi][3], sptr(&AsL[buf][arow][acol]));
        }
#pragma unroll
        for (int np = 0; np < 4; np++) {
            int brow = (lj & 1) * 8 + lr;
            int bcol = wN * 64 + np * 16 + (lj >> 1) * 8;
            ldm4t(bb[np * 2][0], bb[np * 2][1], bb[np * 2 + 1][0], bb[np * 2 + 1][1],
                  sptr(&BsH[buf][brow][bcol]));
        }
#pragma unroll
        for (int mi = 0; mi < 2; mi++)
#pragma unroll
            for (int ni = 0; ni < 8; ni++) {
                mma16816(acc[mi][ni], aH[mi], bb[ni]);
                mma16816(acc[mi][ni], aL[mi], bb[ni]);
            }
#pragma unroll
        for (int np = 0; np < 4; np++) {
            int brow = (lj & 1) * 8 + lr;
            int bcol = wN * 64 + np * 16 + (lj >> 1) * 8;
            ldm4t(bb[np * 2][0], bb[np * 2][1], bb[np * 2 + 1][0], bb[np * 2 + 1][1],
                  sptr(&BsL[buf][brow][bcol]));
        }
#pragma unroll
        for (int mi = 0; mi < 2; mi++)
#pragma unroll
            for (int ni = 0; ni < 8; ni++)
                mma16816(acc[mi][ni], aH[mi], bb[ni]);
    };

    // ---- pipeline: prologue + 1 barrier per k-tile ----
    loadA(0); loadB(0);
    storeTile(0);
    __syncthreads();
    for (int t = 0; t < nt; t++) {
        int cur = t & 1;
        bool more = (t + 1 < nt);
        if (more) { loadA(t + 1); loadB(t + 1); }
        compute(cur);
        if (more) {
            storeTile(cur ^ 1);
            __syncthreads();
        }
    }

    // ---- epilogue ----
    int g = lane >> 2, t4 = lane & 3;
#pragma unroll
    for (int mi = 0; mi < 2; mi++) {
#pragma unroll
        for (int ni = 0; ni < 8; ni++) {
            int col = c0 + wN * 64 + ni * 8 + t4 * 2;
            if (col < M) {
#pragma unroll
                for (int half = 0; half < 2; half++) {
                    int row = r0 + wM * 32 + mi * 16 + g + half * 8;
                    if (row < N) {
                        float v0 = acc[mi][ni][half * 2 + 0];
                        float v1 = acc[mi][ni][half * 2 + 1];
                        if (BIAS) { v0 += bias[col]; v1 += bias[col + 1]; }
                        if (SILU) { v0 = silu_f(v0); v1 = silu_f(v1); }
                        float2 ov = make_float2(v0, v1);
                        *(float2*)&C[(size_t)row * M + col] = ov;
                    }
                }
            }
        }
    }
}

template <bool BIAS, bool SILU>
__global__ void __launch_bounds__(256, 2) mma_gemm_kernel(const float* __restrict__ A,
                                                          const float* __restrict__ B,
                                                          const float* __restrict__ bias,
                                                          float* __restrict__ C,
                                                          int N, int M) {
    mma_gemm_body<BIAS, SILU, false>(A, nullptr, B, bias, C, N, M);
}

__global__ void __launch_bounds__(256, 2) mma_gemm_dual_kernel(const float* __restrict__ A1,
                                                               const float* __restrict__ A2,
                                                               const float* __restrict__ B,
                                                               const float* __restrict__ bias,
                                                               float* __restrict__ C,
                                                               int N) {
    mma_gemm_body<true, true, true>(A1, A2, B, bias, C, N, 128);
}

__global__ void __launch_bounds__(256, 2) mma_gemm_uv_kernel(const float* __restrict__ A,
                                                             const float* __restrict__ B0,
                                                             const float* __restrict__ B1,
                                                             float* __restrict__ C0,
                                                             float* __restrict__ C1,
                                                             int N) {
    const float* B = (blockIdx.z == 0) ? B0 : B1;
    float* C = (blockIdx.z == 0) ? C0 : C1;
    mma_gemm_body<false, false, false>(A, nullptr, B, nullptr, C, N, 128);
}

// ---------------- reset ----------------
__global__ void reset_kernel() { g_nact = 0; }

// ---------------- edge geometry + compaction ----------------
__global__ void edge_geom_kernel(const float* __restrict__ pos,
                                 const float* __restrict__ cell,
                                 const int* __restrict__ ei,
                                 const int* __restrict__ offs,
                                 float* __restrict__ out_dist,
                                 float* __restrict__ out_ei,
                                 int E) {
    int e = blockIdx.x * blockDim.x + threadIdx.x;
    if (e >= E) return;
    int r = ei[e];
    int c = ei[E + e];
    float o0 = (float)offs[e * 3 + 0];
    float o1 = (float)offs[e * 3 + 1];
    float o2 = (float)offs[e * 3 + 2];
    float ox = o0 * cell[0] + o1 * cell[3] + o2 * cell[6];
    float oy = o0 * cell[1] + o1 * cell[4] + o2 * cell[7];
    float oz = o0 * cell[2] + o1 * cell[5] + o2 * cell[8];
    float dx = pos[r * 3 + 0] - pos[c * 3 + 0] + ox;
    float dy = pos[r * 3 + 1] - pos[c * 3 + 1] + oy;
    float dz = pos[r * 3 + 2] - pos[c * 3 + 2] + oz;
    float dist = sqrtf(dx * dx + dy * dy + dz * dz);
    out_dist[e] = dist;
    out_ei[e] = (float)r;
    out_ei[E + e] = (float)c;

    if (dist < CUTOFF) {
        int idx = atomicAdd(&g_nact, 1);
        g_act_r[idx] = r;
        g_act_c[idx] = c;
        float inv = 1.0f / dist;
        g_act_unit[idx * 3 + 0] = dx * inv;
        g_act_unit[idx * 3 + 1] = dy * inv;
        g_act_unit[idx * 3 + 2] = dz * inv;
        g_act_fcut[idx] = 0.5f * (cosf(dist * PI_OVER_CUT) + 1.0f);
#pragma unroll
        for (int t = 0; t < NRBF; t++) {
            g_act_rbf[idx * NRBF + t] = sinf(dist * (float)(t + 1) * PI_OVER_CUT) * inv;
        }
    }
}

// ---------------- node init: ns = embed[z], nv = nvold = 0 ----------------
__global__ void init_nodes_kernel(const float* __restrict__ embed,
                                  const int* __restrict__ z,
                                  int N) {
    int t = blockIdx.x * blockDim.x + threadIdx.x;
    if (t >= N * HID) return;
    int n = t >> 7;
    int h = t & 127;
    g_ns[t] = embed[z[n] * HID + h];
    int base = n * 3 * HID + h;
    g_nv[base] = 0.0f;
    g_nv[base + HID] = 0.0f;
    g_nv[base + 2 * HID] = 0.0f;
    g_nvold[base] = 0.0f;
    g_nvold[base + HID] = 0.0f;
    g_nvold[base + 2 * HID] = 0.0f;
}

// ---------------- edge messages (active edges only, warp per edge) ----------------
__global__ void edge_msg_kernel(const float* __restrict__ W,   // [20,384] for layer l
                                const float* __restrict__ b,   // [384]
                                const float* __restrict__ s) { // [N,384]
    int lane = threadIdx.x & 31;
    int warp = (blockIdx.x * blockDim.x + threadIdx.x) >> 5;
    int nwarps = (gridDim.x * blockDim.x) >> 5;
    int nact = g_nact;
    for (int e = warp; e < nact; e += nwarps) {
        int r = g_act_r[e];
        int c = g_act_c[e];
        float fcut = g_act_fcut[e];
        float u0 = g_act_unit[e * 3 + 0];
        float u1 = g_act_unit[e * 3 + 1];
        float u2 = g_act_unit[e * 3 + 2];
        float rbf[NRBF];
#pragma unroll
        for (int t = 0; t < NRBF; t++) rbf[t] = g_act_rbf[e * NRBF + t];

        float fout[12];
#pragma unroll
        for (int p = 0; p < 12; p++) {
            int j = lane + p * 32;
            float f = b[j];
#pragma unroll
            for (int t = 0; t < NRBF; t++) f += rbf[t] * W[t * 384 + j];
            fout[p] = f * fcut * s[(size_t)c * 384 + j];
        }
#pragma unroll
        for (int q = 0; q < 4; q++) {
            int h = lane + q * 32;
            float gsv = fout[q];
            float gev = fout[4 + q];
            float msg = fout[8 + q];
            atomicAdd(&g_ns[r * HID + h], msg);
            int rb = r * 3 * HID + h;
            int cb = c * 3 * HID + h;
            atomicAdd(&g_nv[rb], g_nvold[cb] * gsv + gev * u0);
            atomicAdd(&g_nv[rb + HID], g_nvold[cb + HID] * gsv + gev * u1);
            atomicAdd(&g_nv[rb + 2 * HID], g_nvold[cb + 2 * HID] * gsv + gev * u2);
        }
    }
}

// ---------------- Vnorm + inner product ----------------
__global__ void vnorm_inner_kernel(int N) {
    int t = blockIdx.x * blockDim.x + threadIdx.x;
    if (t >= N * HID) return;
    int n = t >> 7;
    int h = t & 127;
    size_t base = (size_t)n * 3 * HID + h;
    float u0 = g_Uv[base], u1 = g_Uv[base + HID], u2 = g_Uv[base + 2 * HID];
    float v0 = g_Vv[base], v1 = g_Vv[base + HID], v2 = g_Vv[base + 2 * HID];
    g_Vn[t] = sqrtf(v0 * v0 + v1 * v1 + v2 * v2);
    g_inner[t] = u0 * v0 + u1 * v1 + u2 * v2;
}

// -------- final update: nv += a_vv*Uv ; ns += inner*a_sv + a_ss ; nvold = nv --------
__global__ void update_kernel(int N) {
    int t = blockIdx.x * blockDim.x + threadIdx.x;
    if (t >= N * HID) return;
    int n = t >> 7;
    int h = t & 127;
    size_t base = (size_t)n * 3 * HID + h;
    float avv = g_abuf[base];
    float asv = g_abuf[base + HID];
    float ass = g_abuf[base + 2 * HID];
    float n0 = g_nv[base]           + avv * g_Uv[base];
    float n1 = g_nv[base + HID]     + avv * g_Uv[base + HID];
    float n2 = g_nv[base + 2 * HID] + avv * g_Uv[base + 2 * HID];
    g_nv[base] = n0;            g_nvold[base] = n0;
    g_nv[base + HID] = n1;      g_nvold[base + HID] = n1;
    g_nv[base + 2 * HID] = n2;  g_nvold[base + 2 * HID] = n2;
    g_ns[t] += g_inner[t] * asv + ass;
}

// ---------------- head second layer (matvec over 64) ----------------
__global__ void head2_kernel(const float* __restrict__ w,  // [64]
                             const float* __restrict__ b,  // [1]
                             float* __restrict__ out_v, int N) {
    int n = blockIdx.x * blockDim.x + threadIdx.x;
    if (n >= N) return;
    float acc = b[0];
    const float* h = g_tmpH + (size_t)n * 64;
#pragma unroll
    for (int i = 0; i < 64; i++) acc += h[i] * w[i];
    out_v[n] = acc;
}

// ---------------- launch ----------------
extern "C" void kernel_launch(void* const* d_in, const int* in_sizes, int n_in,
                              void* d_out, int out_size) {
    const int*   z        = (const int*)d_in[0];
    const float* pos      = (const float*)d_in[1];
    const float* cell     = (const float*)d_in[2];
    const int*   ei       = (const int*)d_in[3];
    const int*   offs     = (const int*)d_in[4];
    const float* embed    = (const float*)d_in[5];
    const float* mfW      = (const float*)d_in[6];   // [3,20,384]
    const float* mfb      = (const float*)d_in[7];   // [3,384]
    const float* mW1      = (const float*)d_in[8];   // [3,128,128]
    const float* mb1      = (const float*)d_in[9];
    const float* mW2      = (const float*)d_in[10];  // [3,128,384]
    const float* mb2      = (const float*)d_in[11];
    const float* uU       = (const float*)d_in[12];  // [3,128,128]
    const float* uV       = (const float*)d_in[13];
    const float* uW1      = (const float*)d_in[14];  // [3,256,128]
    const float* ub1      = (const float*)d_in[15];
    const float* uW2      = (const float*)d_in[16];  // [3,128,384]
    const float* ub2      = (const float*)d_in[17];
    const float* hW1      = (const float*)d_in[18];  // [128,64]
    const float* hb1      = (const float*)d_in[19];
    const float* hW2      = (const float*)d_in[20];  // [64]
    const float* hb2      = (const float*)d_in[21];

    int N = in_sizes[0];
    int E = in_sizes[3] / 2;

    float* out   = (float*)d_out;
    float* out_v = out;                  // [N]
    float* out_p = out + N;              // [N*3]
    float* out_e = out + 4 * N;          // [2*E]
    float* out_d = out + 4 * N + 2 * E;  // [E]

    void* p;
    cudaGetSymbolAddress(&p, g_ns);    float* ns    = (float*)p;
    cudaGetSymbolAddress(&p, g_nv);    float* nv    = (float*)p;
    cudaGetSymbolAddress(&p, g_tmpH);  float* tmpH  = (float*)p;
    cudaGetSymbolAddress(&p, g_smsg);  float* smsg  = (float*)p;
    cudaGetSymbolAddress(&p, g_Uv);    float* Uv    = (float*)p;
    cudaGetSymbolAddress(&p, g_Vv);    float* Vv    = (float*)p;
    cudaGetSymbolAddress(&p, g_Vn);    float* Vn    = (float*)p;
    cudaGetSymbolAddress(&p, g_abuf);  float* abuf  = (float*)p;

    int RT = (N + 127) / 128;
    int RT3 = (3 * N + 127) / 128;

    reset_kernel<<<1, 1>>>();
    edge_geom_kernel<<<(E + 255) / 256, 256>>>(pos, cell, ei, offs, out_d, out_e, E);
    init_nodes_kernel<<<(N * HID + 255) / 256, 256>>>(embed, z, N);
    cudaMemcpyAsync(out_p, pos, (size_t)N * 3 * sizeof(float), cudaMemcpyDeviceToDevice);

    for (int l = 0; l < 3; l++) {
        const float* lmfW = mfW + (size_t)l * 20 * 384;
        const float* lmfb = mfb + (size_t)l * 384;

        // tmpH = silu(ns @ mW1 + mb1)
        mma_gemm_kernel<true, true><<<dim3(1, RT), 256>>>(
            ns, mW1 + (size_t)l * 128 * 128, mb1 + (size_t)l * 128, tmpH, N, 128);
        // smsg = tmpH @ mW2 + mb2
        mma_gemm_kernel<true, false><<<dim3(3, RT), 256>>>(
            tmpH, mW2 + (size_t)l * 128 * 384, mb2 + (size_t)l * 384, smsg, N, 384);

        // edge messages read g_nvold (pre-message state, maintained by dual-write)
        edge_msg_kernel<<<256, 256>>>(lmfW, lmfb, smsg);

        // Uv = nv @ uU ; Vv = nv @ uV  (nv viewed as [3N,128]; z selects B/C)
        mma_gemm_uv_kernel<<<dim3(1, RT3, 2), 256>>>(
            nv, uU + (size_t)l * 128 * 128, uV + (size_t)l * 128 * 128, Uv, Vv, 3 * N);

        vnorm_inner_kernel<<<(N * HID + 255) / 256, 256>>>(N);

        // tmpH = silu([ns|Vn] @ uW1 + ub1)   (dual-A, K=256)
        mma_gemm_dual_kernel<<<dim3(1, RT), 256>>>(
            ns, Vn, uW1 + (size_t)l * 256 * 128, ub1 + (size_t)l * 128, tmpH, N);
        // abuf = tmpH @ uW2 + ub2
        mma_gemm_kernel<true, false><<<dim3(3, RT), 256>>>(
            tmpH, uW2 + (size_t)l * 128 * 384, ub2 + (size_t)l * 384, abuf, N, 384);

        update_kernel<<<(N * HID + 255) / 256, 256>>>(N);
    }

    // head: tmpH[:, :64] = silu(ns @ hW1 + hb1)   (M=64 guarded in epilogue)
    mma_gemm_kernel<true, true><<<dim3(1, RT), 256>>>(ns, hW1, hb1, tmpH, N, 64);
    head2_kernel<<<(N + 255) / 256, 256>>>(hW2, hb2, out_v, N);
}